// round 16
// baseline (speedup 1.0000x reference)
#include <cuda_runtime.h>
#include <cuda_fp16.h>

// Problem constants
#define VSZ   30000
#define OC    128
#define KW    5
#define BATCH 32

constexpr int L    = 2560;          // 40*64 flattened token positions per batch
constexpr int LOUT = L - KW + 1;    // 2556
constexpr int CW   = VSZ * KW;      // 150000 columns (v*5+w)
constexpr int NSUB = 128;           // sub-chunks of the l-range
constexpr int SUBL = 20;            // 128*20 = 2560 >= LOUT

// Scratch: transposed fp16 table Kt[v][w][oc]  (38.4 MB, L2-resident)
__device__ __align__(16) __half g_Kt[(size_t)VSZ * KW * OC];
// Pooled relu-max as float bits (all values >= 0 -> int-compare == float max)
__device__ int g_pooled[BATCH][OC];

// ---------------------------------------------------------------------------
// Kernel 1: transpose + fp32->fp16 convert (R8/R14 winner — at mixed-stream
// DRAM ceiling). Also zeroes g_pooled (blocks 0..31) so conv can RED.MAX
// into it; transpose strictly precedes conv, so this is race-free and
// deterministic per launch.
// K is (128 x 150000), row = oc, col = v*5+w.  ->  Kt[col][oc] as half.
// ---------------------------------------------------------------------------
__global__ void __launch_bounds__(256) transpose_kernel(const float* __restrict__ src) {
    __shared__ unsigned tile[64][65];         // [col-local][oc-pair 0..63]
    const int t     = threadIdx.x;
    const int rp0   = t >> 4;                 // 0..15
    const int c4    = (t & 15) * 4;           // column group within tile
    const int cbase = blockIdx.x * 64;
    const int c     = cbase + c4;
    const bool cok  = (c + 3 < CW);           // whole float4 in range (CW%4==0)

    if (blockIdx.x < BATCH && t < OC)
        g_pooled[blockIdx.x][t] = 0;          // float 0.0 bits

    #pragma unroll
    for (int i = 0; i < 4; i++) {
        const int RP = rp0 + 16 * i;          // rowpair 0..63 -> rows 2RP, 2RP+1
        if (cok) {
            const float4 fa = __ldcs(reinterpret_cast<const float4*>(
                                  src + (size_t)(2 * RP)     * CW + c));
            const float4 fb = __ldcs(reinterpret_cast<const float4*>(
                                  src + (size_t)(2 * RP + 1) * CW + c));
            half2 h0 = __floats2half2_rn(fa.x, fb.x);
            half2 h1 = __floats2half2_rn(fa.y, fb.y);
            half2 h2 = __floats2half2_rn(fa.z, fb.z);
            half2 h3 = __floats2half2_rn(fa.w, fb.w);
            tile[c4 + 0][RP] = *reinterpret_cast<unsigned*>(&h0);
            tile[c4 + 1][RP] = *reinterpret_cast<unsigned*>(&h1);
            tile[c4 + 2][RP] = *reinterpret_cast<unsigned*>(&h2);
            tile[c4 + 3][RP] = *reinterpret_cast<unsigned*>(&h3);
        }
    }
    __syncthreads();

    // Write out: 64 Kt rows x 64 uints (128 halfs) each.
    const int colu   = t & 63;                // uint (rowpair) index in Kt row
    const int rowsel = t >> 6;                // 0..3
    #pragma unroll
    for (int i = 0; i < 16; i++) {
        int row = rowsel + i * 4;             // col-local 0..63
        int vw  = cbase + row;
        if (vw < CW)
            reinterpret_cast<unsigned*>(g_Kt)[(size_t)vw * 64 + colu] = tile[row][colu];
    }
}

// ---------------------------------------------------------------------------
// Kernel 2: gather + sliding-window conv + relu-max (R10/R14 winner inner
// loop). grid = (NSUB/4, BATCH), 128-thr blocks; one warp per sub-chunk;
// lane owns 4 oc as one uint2 -> 5 x 256B L2 sectors per token.
// NEW: pooled max is fused here via no-return atomicMax on float bits
// (valid: all values >= 0), eliminating the g_partial round-trip and the
// final kernel's serial 64-step scan.
// Ring-slot reset MUST be unconditional (boundary-pollution flush, see R3).
// ---------------------------------------------------------------------------
__device__ __forceinline__ void addh4(float4& a, const uint2 v) {
    const half2 h0 = *reinterpret_cast<const half2*>(&v.x);
    const half2 h1 = *reinterpret_cast<const half2*>(&v.y);
    float2 f0 = __half22float2(h0);
    float2 f1 = __half22float2(h1);
    a.x += f0.x; a.y += f0.y; a.z += f1.x; a.w += f1.y;
}
__device__ __forceinline__ void max4(float4& a, const float4 b) {
    a.x = fmaxf(a.x, b.x); a.y = fmaxf(a.y, b.y);
    a.z = fmaxf(a.z, b.z); a.w = fmaxf(a.w, b.w);
}

__global__ void __launch_bounds__(128) conv_kernel(const int* __restrict__ tokens) {
    const int b    = blockIdx.y;
    const int warp = threadIdx.x >> 5;
    const int lane = threadIdx.x & 31;
    const int sub  = blockIdx.x * 4 + warp;

    const int l0 = sub * SUBL;
    const int l1 = min(l0 + SUBL, LOUT);
    const int n  = l1 + KW - 1 - l0;     // tokens this sub-chunk (<= 24)

    const int* ids = tokens + b * L;
    int myid = 0;
    if (lane < n) myid = __ldg(ids + l0 + lane);

    const uint2* __restrict__ Kt8 = reinterpret_cast<const uint2*>(g_Kt);

    float4 acc[5];
    #pragma unroll
    for (int i = 0; i < 5; i++) acc[i] = make_float4(0.f, 0.f, 0.f, 0.f);
    float4 vmax = make_float4(0.f, 0.f, 0.f, 0.f);   // relu: floor at 0

    #pragma unroll
    for (int j = 0; j < SUBL + KW - 1; j++) {       // j = p - l0
        if (j < n) {
            int id = __shfl_sync(0xFFFFFFFFu, myid, j);
            // 640 halfs per token row = 160 uint2; w-row = 32 uint2.
            const uint2* srcp = Kt8 + (size_t)id * 160 + lane;
            uint2 v0 = __ldg(srcp +   0);
            uint2 v1 = __ldg(srcp +  32);
            uint2 v2 = __ldg(srcp +  64);
            uint2 v3 = __ldg(srcp +  96);
            uint2 v4 = __ldg(srcp + 128);
            // conv[l = p - w] += K[:, id, w]; slot(l) = (l - l0) mod 5
            addh4(acc[(j + 5 - 0) % 5], v0);
            addh4(acc[(j + 5 - 1) % 5], v1);
            addh4(acc[(j + 5 - 2) % 5], v2);
            addh4(acc[(j + 5 - 3) % 5], v3);
            addh4(acc[(j + 5 - 4) % 5], v4);
            // slot (j+1)%5: completed conv[p-4] when j>=4; stale boundary
            // pollution when j<4 — reset it either way.
            const int s = (j + 1) % 5;
            if (j >= 4) max4(vmax, acc[s]);
            acc[s] = make_float4(0.f, 0.f, 0.f, 0.f);
        }
    }
    // Fused max-pool: float-as-int atomicMax (values >= 0), no return -> RED.
    int* dst = &g_pooled[b][lane * 4];
    atomicMax(dst + 0, __float_as_int(vmax.x));
    atomicMax(dst + 1, __float_as_int(vmax.y));
    atomicMax(dst + 2, __float_as_int(vmax.z));
    atomicMax(dst + 3, __float_as_int(vmax.w));
}

// ---------------------------------------------------------------------------
// Kernel 3: tiny FC from the fused pooled maxima. grid = 32 (b), block = 128.
// ---------------------------------------------------------------------------
__global__ void __launch_bounds__(128) final_kernel(const float* __restrict__ fc1_w,
                                                    const float* __restrict__ fc1_b,
                                                    float* __restrict__ out) {
    const int b  = blockIdx.x;
    const int t  = threadIdx.x;          // = oc
    const int warp = t >> 5, lane = t & 31;

    float pooled = __int_as_float(g_pooled[b][t]);

    __shared__ float shw[4][4];          // [warp][tc]
    #pragma unroll
    for (int tc = 0; tc < 4; tc++) {
        float v = pooled * fc1_w[tc * OC + t];
        #pragma unroll
        for (int off = 16; off > 0; off >>= 1)
            v += __shfl_down_sync(0xFFFFFFFFu, v, off);
        if (lane == 0) shw[warp][tc] = v;
    }
    __syncthreads();
    if (t < 4) {
        float s = shw[0][t] + shw[1][t] + shw[2][t] + shw[3][t];
        out[b * 4 + t] = s + fc1_b[t];
    }
}

// ---------------------------------------------------------------------------
extern "C" void kernel_launch(void* const* d_in, const int* in_sizes, int n_in,
                              void* d_out, int out_size) {
    const int*   tokens = (const int*)  d_in[0];
    const float* k1     = (const float*)d_in[1];
    const float* fc1w   = (const float*)d_in[2];
    const float* fc1b   = (const float*)d_in[3];
    float*       out    = (float*)d_out;

    transpose_kernel<<<(CW + 63) / 64, 256>>>(k1);        // 2344 blocks

    conv_kernel<<<dim3(NSUB / 4, BATCH), 128>>>(tokens);  // (32, 32) = 1024 blocks

    final_kernel<<<BATCH, 128>>>(fc1w, fc1b, out);
}

// round 17
// speedup vs baseline: 1.0504x; 1.0504x over previous
#include <cuda_runtime.h>
#include <cuda_fp16.h>

// Problem constants
#define VSZ   30000
#define OC    128
#define KW    5
#define BATCH 32

constexpr int L    = 2560;          // 40*64 flattened token positions per batch
constexpr int LOUT = L - KW + 1;    // 2556
constexpr int CW   = VSZ * KW;      // 150000 columns (v*5+w)
constexpr int NSUB = 128;           // sub-chunks of the l-range
constexpr int SUBL = 20;            // 128*20 = 2560 >= LOUT
constexpr int CBLK = NSUB / 4;      // 32 conv blocks per batch

// Scratch: transposed fp16 table Kt[v][w][oc]  (38.4 MB, L2-resident)
__device__ __align__(16) __half g_Kt[(size_t)VSZ * KW * OC];
// Per-warp partial maxima: [b][sub][oc]
__device__ float g_partial[BATCH][NSUB][OC];
// Per-batch conv-block completion counters (zeroed by transpose each call)
__device__ int g_cnt[BATCH];

// ---------------------------------------------------------------------------
// Kernel 1: transpose + fp32->fp16 convert (R8/R14 winner — at mixed-stream
// DRAM ceiling). Block 0 also zeroes the per-batch completion counters;
// transpose strictly precedes conv, so this is race-free and deterministic.
// K is (128 x 150000), row = oc, col = v*5+w.  ->  Kt[col][oc] as half.
// ---------------------------------------------------------------------------
__global__ void __launch_bounds__(256) transpose_kernel(const float* __restrict__ src) {
    __shared__ unsigned tile[64][65];         // [col-local][oc-pair 0..63]
    const int t     = threadIdx.x;
    const int rp0   = t >> 4;                 // 0..15
    const int c4    = (t & 15) * 4;           // column group within tile
    const int cbase = blockIdx.x * 64;
    const int c     = cbase + c4;
    const bool cok  = (c + 3 < CW);           // whole float4 in range (CW%4==0)

    if (blockIdx.x == 0 && t < BATCH)
        g_cnt[t] = 0;

    #pragma unroll
    for (int i = 0; i < 4; i++) {
        const int RP = rp0 + 16 * i;          // rowpair 0..63 -> rows 2RP, 2RP+1
        if (cok) {
            const float4 fa = __ldcs(reinterpret_cast<const float4*>(
                                  src + (size_t)(2 * RP)     * CW + c));
            const float4 fb = __ldcs(reinterpret_cast<const float4*>(
                                  src + (size_t)(2 * RP + 1) * CW + c));
            half2 h0 = __floats2half2_rn(fa.x, fb.x);
            half2 h1 = __floats2half2_rn(fa.y, fb.y);
            half2 h2 = __floats2half2_rn(fa.z, fb.z);
            half2 h3 = __floats2half2_rn(fa.w, fb.w);
            tile[c4 + 0][RP] = *reinterpret_cast<unsigned*>(&h0);
            tile[c4 + 1][RP] = *reinterpret_cast<unsigned*>(&h1);
            tile[c4 + 2][RP] = *reinterpret_cast<unsigned*>(&h2);
            tile[c4 + 3][RP] = *reinterpret_cast<unsigned*>(&h3);
        }
    }
    __syncthreads();

    // Write out: 64 Kt rows x 64 uints (128 halfs) each.
    const int colu   = t & 63;                // uint (rowpair) index in Kt row
    const int rowsel = t >> 6;                // 0..3
    #pragma unroll
    for (int i = 0; i < 16; i++) {
        int row = rowsel + i * 4;             // col-local 0..63
        int vw  = cbase + row;
        if (vw < CW)
            reinterpret_cast<unsigned*>(g_Kt)[(size_t)vw * 64 + colu] = tile[row][colu];
    }
}

// ---------------------------------------------------------------------------
// Kernel 2: gather + sliding-window conv + relu-max (R10/R14 winner inner
// loop) + FUSED per-batch reduction/FC in the last-finishing block.
// grid = (CBLK, BATCH), 128-thr blocks; one warp per sub-chunk; lane owns
// 4 oc as one uint2 -> 5 x 256B L2 sectors per token.
// After storing partials each block release-arrives on g_cnt[b]; the 32nd
// arrival acquire-fences and performs the 128-sub max-scan + shuffle FC,
// writing out[b] — removing the separate final kernel + its launch gap.
// Ring-slot reset MUST be unconditional (boundary-pollution flush, see R3).
// ---------------------------------------------------------------------------
__device__ __forceinline__ void addh4(float4& a, const uint2 v) {
    const half2 h0 = *reinterpret_cast<const half2*>(&v.x);
    const half2 h1 = *reinterpret_cast<const half2*>(&v.y);
    float2 f0 = __half22float2(h0);
    float2 f1 = __half22float2(h1);
    a.x += f0.x; a.y += f0.y; a.z += f1.x; a.w += f1.y;
}
__device__ __forceinline__ void max4(float4& a, const float4 b) {
    a.x = fmaxf(a.x, b.x); a.y = fmaxf(a.y, b.y);
    a.z = fmaxf(a.z, b.z); a.w = fmaxf(a.w, b.w);
}

__global__ void __launch_bounds__(128) conv_kernel(const int* __restrict__ tokens,
                                                   const float* __restrict__ fc1_w,
                                                   const float* __restrict__ fc1_b,
                                                   float* __restrict__ out) {
    const int b    = blockIdx.y;
    const int warp = threadIdx.x >> 5;
    const int lane = threadIdx.x & 31;
    const int sub  = blockIdx.x * 4 + warp;

    const int l0 = sub * SUBL;
    const int l1 = min(l0 + SUBL, LOUT);
    const int n  = l1 + KW - 1 - l0;     // tokens this sub-chunk (<= 24)

    const int* ids = tokens + b * L;
    int myid = 0;
    if (lane < n) myid = __ldg(ids + l0 + lane);

    const uint2* __restrict__ Kt8 = reinterpret_cast<const uint2*>(g_Kt);

    float4 acc[5];
    #pragma unroll
    for (int i = 0; i < 5; i++) acc[i] = make_float4(0.f, 0.f, 0.f, 0.f);
    float4 vmax = make_float4(0.f, 0.f, 0.f, 0.f);   // relu: floor at 0

    #pragma unroll
    for (int j = 0; j < SUBL + KW - 1; j++) {       // j = p - l0
        if (j < n) {
            int id = __shfl_sync(0xFFFFFFFFu, myid, j);
            // 640 halfs per token row = 160 uint2; w-row = 32 uint2.
            const uint2* srcp = Kt8 + (size_t)id * 160 + lane;
            uint2 v0 = __ldg(srcp +   0);
            uint2 v1 = __ldg(srcp +  32);
            uint2 v2 = __ldg(srcp +  64);
            uint2 v3 = __ldg(srcp +  96);
            uint2 v4 = __ldg(srcp + 128);
            // conv[l = p - w] += K[:, id, w]; slot(l) = (l - l0) mod 5
            addh4(acc[(j + 5 - 0) % 5], v0);
            addh4(acc[(j + 5 - 1) % 5], v1);
            addh4(acc[(j + 5 - 2) % 5], v2);
            addh4(acc[(j + 5 - 3) % 5], v3);
            addh4(acc[(j + 5 - 4) % 5], v4);
            // slot (j+1)%5: completed conv[p-4] when j>=4; stale boundary
            // pollution when j<4 — reset it either way.
            const int s = (j + 1) % 5;
            if (j >= 4) max4(vmax, acc[s]);
            acc[s] = make_float4(0.f, 0.f, 0.f, 0.f);
        }
    }
    float4* dst = reinterpret_cast<float4*>(&g_partial[b][sub][0]);
    dst[lane] = vmax;

    // ---- completion protocol: release-arrive on this batch's counter ----
    __threadfence();                     // publish g_partial stores
    __shared__ int s_last;
    __syncthreads();                     // all warps' stores issued
    if (threadIdx.x == 0)
        s_last = (atomicAdd(&g_cnt[b], 1) == CBLK - 1);
    __syncthreads();
    if (!s_last) return;
    __threadfence();                     // acquire: see other blocks' partials

    // ---- fused reduction + FC for batch b (one 128-thr block) ----
    const int t = threadIdx.x;           // = oc
    const float* part = &g_partial[b][0][0];   // [NSUB][128]
    float pooled = 0.f;
    #pragma unroll 8
    for (int s = 0; s < NSUB; s++)
        pooled = fmaxf(pooled, part[s * OC + t]);

    __shared__ float shw[4][4];          // [warp][tc]
    #pragma unroll
    for (int tc = 0; tc < 4; tc++) {
        float v = pooled * fc1_w[tc * OC + t];
        #pragma unroll
        for (int off = 16; off > 0; off >>= 1)
            v += __shfl_down_sync(0xFFFFFFFFu, v, off);
        if (lane == 0) shw[warp][tc] = v;
    }
    __syncthreads();
    if (t < 4)
        out[b * 4 + t] = shw[0][t] + shw[1][t] + shw[2][t] + shw[3][t] + fc1_b[t];
}

// ---------------------------------------------------------------------------
extern "C" void kernel_launch(void* const* d_in, const int* in_sizes, int n_in,
                              void* d_out, int out_size) {
    const int*   tokens = (const int*)  d_in[0];
    const float* k1     = (const float*)d_in[1];
    const float* fc1w   = (const float*)d_in[2];
    const float* fc1b   = (const float*)d_in[3];
    float*       out    = (float*)d_out;

    transpose_kernel<<<(CW + 63) / 64, 256>>>(k1);        // 2344 blocks

    conv_kernel<<<dim3(CBLK, BATCH), 128>>>(tokens, fc1w, fc1b, out);
}